// round 5
// baseline (speedup 1.0000x reference)
#include <cuda_runtime.h>

#define TPB 128
// per-sample smem stride (odd => conflict-free rows): euler in, positions out.
// e[0..47] consumed sequentially; o[j..j+2] overwrites slots j-3..j-1;
// root o[0..2] -> slots 48..50.
#define EOSTR 51

__device__ __forceinline__ void euler_R(float ax, float ay, float az, float R[9]) {
    float sx, cx, sy, cy, sz, cz;
    __sincosf(ax, &sx, &cx);
    __sincosf(ay, &sy, &cy);
    __sincosf(az, &sz, &cz);
    float sxsy = sx * sy;
    float cxsy = cx * sy;
    R[0] = cy * cz;                 R[1] = -cy * sz;                 R[2] = sy;
    R[3] = fmaf(sxsy, cz, cx * sz); R[4] = fmaf(-sxsy, sz, cx * cz); R[5] = -sx * cy;
    R[6] = fmaf(-cxsy, cz, sx * sz);R[7] = fmaf(cxsy, sz, sx * cz);  R[8] = cx * cy;
}

__device__ __forceinline__ void compose(const float Mp[9], const float R[9], float Mc[9]) {
#pragma unroll
    for (int i = 0; i < 3; i++) {
#pragma unroll
        for (int j = 0; j < 3; j++) {
            Mc[i * 3 + j] = fmaf(Mp[i * 3 + 0], R[0 + j],
                            fmaf(Mp[i * 3 + 1], R[3 + j],
                                 Mp[i * 3 + 2] * R[6 + j]));
        }
    }
}

// write joint position floats j..j+2 into slots j-3..j-1
__device__ __forceinline__ void put3(float* o, int j, float x, float y, float z) {
    o[j - 3] = x; o[j - 2] = y; o[j - 1] = z;
}

extern "C" __global__ void __launch_bounds__(TPB, 8)
fk_kernel(const float* __restrict__ euler, const float* __restrict__ blen,
          float* __restrict__ out, int N)
{
    extern __shared__ float sm[];
    float* s_eo = sm;                      // TPB * EOSTR

    const int t    = threadIdx.x;
    const int base = blockIdx.x * TPB;
    const int ns   = min(TPB, N - base);

    // ---- euler load: scalar, coalesced in GMEM, stride-1 lanes in smem ----
    {
        const float* ge = euler + (size_t)base * 48;
        const int nfe = ns * 48;
#pragma unroll 4
        for (int g = t; g < nfe; g += TPB) {
            int s = g / 48;
            int r = g - s * 48;
            s_eo[s * EOSTR + r] = ge[g];
        }
    }

    // ---- bone lengths: per-thread direct float4 loads (no smem) ----
    float L[16];
    if (t < ns) {
        const float4* gb = (const float4*)(blen + (size_t)(base + t) * 16);
        float4 a = gb[0], b = gb[1], c = gb[2], d = gb[3];
        L[0]=a.x; L[1]=a.y; L[2]=a.z; L[3]=a.w;
        L[4]=b.x; L[5]=b.y; L[6]=b.z; L[7]=b.w;
        L[8]=c.x; L[9]=c.y; L[10]=c.z; L[11]=c.w;
        L[12]=d.x; L[13]=d.y; L[14]=d.z; L[15]=d.w;
    }
    __syncthreads();

    // ---- per-sample forward kinematics (in-place: o[j] -> slot j-3) ----
    if (t < ns) {
        float* eo = s_eo + t * EOSTR;

        float R[9], MA[9], MB[9], M8[9];
        float px, py, pz, p8x, p8y, p8z;

        // leg 1: bones 0,1,2 -> joints 1,2,3 (parent=root, M=I)
        euler_R(eo[0], eo[1], eo[2], MA);
        px = L[0] * MA[6]; py = L[0] * MA[7]; pz = L[0] * MA[8];
        put3(eo, 3, px, py, pz);
        euler_R(eo[3], eo[4], eo[5], R);  compose(MA, R, MB);
        px = fmaf(L[1], MB[6], px); py = fmaf(L[1], MB[7], py); pz = fmaf(L[1], MB[8], pz);
        put3(eo, 6, px, py, pz);
        euler_R(eo[6], eo[7], eo[8], R);  compose(MB, R, MA);
        px = fmaf(L[2], MA[6], px); py = fmaf(L[2], MA[7], py); pz = fmaf(L[2], MA[8], pz);
        put3(eo, 9, px, py, pz);

        // leg 2: bones 3,4,5 -> joints 4,5,6
        euler_R(eo[9], eo[10], eo[11], MA);
        px = L[3] * MA[6]; py = L[3] * MA[7]; pz = L[3] * MA[8];
        put3(eo, 12, px, py, pz);
        euler_R(eo[12], eo[13], eo[14], R); compose(MA, R, MB);
        px = fmaf(L[4], MB[6], px); py = fmaf(L[4], MB[7], py); pz = fmaf(L[4], MB[8], pz);
        put3(eo, 15, px, py, pz);
        euler_R(eo[15], eo[16], eo[17], R); compose(MB, R, MA);
        px = fmaf(L[5], MA[6], px); py = fmaf(L[5], MA[7], py); pz = fmaf(L[5], MA[8], pz);
        put3(eo, 18, px, py, pz);

        // spine: bone 6 (0->7), bone 7 (7->8)
        euler_R(eo[18], eo[19], eo[20], MA);
        px = L[6] * MA[6]; py = L[6] * MA[7]; pz = L[6] * MA[8];
        put3(eo, 21, px, py, pz);
        euler_R(eo[21], eo[22], eo[23], R); compose(MA, R, M8);
        p8x = fmaf(L[7], M8[6], px); p8y = fmaf(L[7], M8[7], py); p8z = fmaf(L[7], M8[8], pz);
        put3(eo, 24, p8x, p8y, p8z);

        // head: bones 8 (8->9), 9 (9->10) -> joints 9,10
        euler_R(eo[24], eo[25], eo[26], R); compose(M8, R, MA);
        px = fmaf(L[8], MA[6], p8x); py = fmaf(L[8], MA[7], p8y); pz = fmaf(L[8], MA[8], p8z);
        put3(eo, 27, px, py, pz);
        euler_R(eo[27], eo[28], eo[29], R); compose(MA, R, MB);
        px = fmaf(L[9], MB[6], px); py = fmaf(L[9], MB[7], py); pz = fmaf(L[9], MB[8], pz);
        put3(eo, 30, px, py, pz);

        // arm A: bones 10,11,12 (8->11->12->13) -> joints 11,12,13
        euler_R(eo[30], eo[31], eo[32], R); compose(M8, R, MA);
        px = fmaf(L[10], MA[6], p8x); py = fmaf(L[10], MA[7], p8y); pz = fmaf(L[10], MA[8], p8z);
        put3(eo, 33, px, py, pz);
        euler_R(eo[33], eo[34], eo[35], R); compose(MA, R, MB);
        px = fmaf(L[11], MB[6], px); py = fmaf(L[11], MB[7], py); pz = fmaf(L[11], MB[8], pz);
        put3(eo, 36, px, py, pz);
        euler_R(eo[36], eo[37], eo[38], R); compose(MB, R, MA);
        px = fmaf(L[12], MA[6], px); py = fmaf(L[12], MA[7], py); pz = fmaf(L[12], MA[8], pz);
        put3(eo, 39, px, py, pz);

        // arm B: bones 13,14,15 (8->14->15->16) -> joints 14,15,16
        euler_R(eo[39], eo[40], eo[41], R); compose(M8, R, MA);
        px = fmaf(L[13], MA[6], p8x); py = fmaf(L[13], MA[7], p8y); pz = fmaf(L[13], MA[8], p8z);
        put3(eo, 42, px, py, pz);
        euler_R(eo[42], eo[43], eo[44], R); compose(MA, R, MB);
        px = fmaf(L[14], MB[6], px); py = fmaf(L[14], MB[7], py); pz = fmaf(L[14], MB[8], pz);
        put3(eo, 45, px, py, pz);
        euler_R(eo[45], eo[46], eo[47], R); compose(MB, R, MA);
        px = fmaf(L[15], MA[6], px); py = fmaf(L[15], MA[7], py); pz = fmaf(L[15], MA[8], pz);
        put3(eo, 48, px, py, pz);   // o[48..50] -> slots 45..47

        // root joint o[0..2] -> slots 48..50 (written last; slots never used by euler)
        eo[48] = 0.f; eo[49] = 0.f; eo[50] = 0.f;
    }
    __syncthreads();

    // ---- store: scalar, stride-1 lanes in both smem and GMEM ----
    // output float j of sample s lives at slot (j>=3 ? j-3 : j+48)
    {
        float* go = out + (size_t)base * 51;
        const int nf = ns * 51;
#pragma unroll 4
        for (int g = t; g < nf; g += TPB) {
            int s = g / 51;
            int r = g - s * 51;
            int slot = (r >= 3) ? (r - 3) : (r + 48);
            go[g] = s_eo[s * EOSTR + slot];
        }
    }
}

extern "C" void kernel_launch(void* const* d_in, const int* in_sizes, int n_in,
                              void* d_out, int out_size)
{
    const float* euler = (const float*)d_in[0];   // (N,16,3) f32
    const float* blen  = (const float*)d_in[1];   // (N,16,1) f32
    float* out = (float*)d_out;                   // (N,17,3) f32

    const int N = in_sizes[0] / 48;
    const int grid = (N + TPB - 1) / TPB;
    const size_t smem = (size_t)TPB * EOSTR * sizeof(float); // 26,112 B -> 8 blocks/SM

    cudaFuncSetAttribute(fk_kernel, cudaFuncAttributeMaxDynamicSharedMemorySize, (int)smem);
    cudaFuncSetAttribute(fk_kernel, cudaFuncAttributePreferredSharedMemoryCarveout,
                         cudaSharedmemCarveoutMaxShared);
    fk_kernel<<<grid, TPB, smem>>>(euler, blen, out, N);
}

// round 6
// speedup vs baseline: 1.2101x; 1.2101x over previous
#include <cuda_runtime.h>

#define TPB 128
// per-sample smem strides (odd => conflict-free for both scalar rows and
// float4 phased access): euler-in / positions-out buffer, and lengths buffer.
#define EOSTR 51  // e[0..47] consumed sequentially; o[j..j+2] -> slots j-3..j-1;
                  // root o[0..2] -> slots 48..50
#define BSTR 17

__device__ __forceinline__ void euler_R(float ax, float ay, float az, float R[9]) {
    float sx, cx, sy, cy, sz, cz;
    __sincosf(ax, &sx, &cx);
    __sincosf(ay, &sy, &cy);
    __sincosf(az, &sz, &cz);
    float sxsy = sx * sy;
    float cxsy = cx * sy;
    R[0] = cy * cz;                 R[1] = -cy * sz;                 R[2] = sy;
    R[3] = fmaf(sxsy, cz, cx * sz); R[4] = fmaf(-sxsy, sz, cx * cz); R[5] = -sx * cy;
    R[6] = fmaf(-cxsy, cz, sx * sz);R[7] = fmaf(cxsy, sz, sx * cz);  R[8] = cx * cy;
}

__device__ __forceinline__ void compose(const float Mp[9], const float R[9], float Mc[9]) {
#pragma unroll
    for (int i = 0; i < 3; i++) {
#pragma unroll
        for (int j = 0; j < 3; j++) {
            Mc[i * 3 + j] = fmaf(Mp[i * 3 + 0], R[0 + j],
                            fmaf(Mp[i * 3 + 1], R[3 + j],
                                 Mp[i * 3 + 2] * R[6 + j]));
        }
    }
}

// write joint position floats j..j+2 into slots j-3..j-1
__device__ __forceinline__ void put3(float* o, int j, float x, float y, float z) {
    o[j - 3] = x; o[j - 2] = y; o[j - 1] = z;
}

extern "C" __global__ void __launch_bounds__(TPB)
fk_kernel(const float* __restrict__ euler, const float* __restrict__ blen,
          float* __restrict__ out, int N)
{
    extern __shared__ float sm[];
    float* s_eo = sm;                      // TPB * EOSTR (euler in, positions out)
    float* s_b  = s_eo + TPB * EOSTR;      // TPB * BSTR  (bone lengths)

    const int t    = threadIdx.x;
    const int base = blockIdx.x * TPB;
    const int ns   = min(TPB, N - base);

    // ---- euler load: float4, coalesced GMEM, conflict-free phased STS ----
    {
        const float4* ge = (const float4*)(euler + (size_t)base * 48);
        const int ne4 = ns * 12;
#pragma unroll 12
        for (int i = t; i < ne4; i += TPB) {
            float4 v = ge[i];
            int s = i / 12, r = i - s * 12;
            float* p = s_eo + s * EOSTR + r * 4;
            p[0] = v.x; p[1] = v.y; p[2] = v.z; p[3] = v.w;
        }
    }
    // ---- bone lengths: float4 staging ----
    {
        const float4* gb = (const float4*)(blen + (size_t)base * 16);
        const int nb4 = ns * 4;
#pragma unroll 4
        for (int i = t; i < nb4; i += TPB) {
            float4 v = gb[i];
            int s = i >> 2, r = i & 3;
            float* p = s_b + s * BSTR + r * 4;
            p[0] = v.x; p[1] = v.y; p[2] = v.z; p[3] = v.w;
        }
    }
    __syncthreads();

    // ---- per-sample forward kinematics (in-place: o[j] -> slot j-3) ----
    if (t < ns) {
        float* eo = s_eo + t * EOSTR;
        const float* L = s_b + t * BSTR;   // scalar LDS at use, conflict-free rows

        float R[9], MA[9], MB[9], M8[9];
        float px, py, pz, p8x, p8y, p8z;

        // leg 1: bones 0,1,2 -> joints 1,2,3 (parent=root, M=I)
        euler_R(eo[0], eo[1], eo[2], MA);
        px = L[0] * MA[6]; py = L[0] * MA[7]; pz = L[0] * MA[8];
        put3(eo, 3, px, py, pz);
        euler_R(eo[3], eo[4], eo[5], R);  compose(MA, R, MB);
        px = fmaf(L[1], MB[6], px); py = fmaf(L[1], MB[7], py); pz = fmaf(L[1], MB[8], pz);
        put3(eo, 6, px, py, pz);
        euler_R(eo[6], eo[7], eo[8], R);  compose(MB, R, MA);
        px = fmaf(L[2], MA[6], px); py = fmaf(L[2], MA[7], py); pz = fmaf(L[2], MA[8], pz);
        put3(eo, 9, px, py, pz);

        // leg 2: bones 3,4,5 -> joints 4,5,6
        euler_R(eo[9], eo[10], eo[11], MA);
        px = L[3] * MA[6]; py = L[3] * MA[7]; pz = L[3] * MA[8];
        put3(eo, 12, px, py, pz);
        euler_R(eo[12], eo[13], eo[14], R); compose(MA, R, MB);
        px = fmaf(L[4], MB[6], px); py = fmaf(L[4], MB[7], py); pz = fmaf(L[4], MB[8], pz);
        put3(eo, 15, px, py, pz);
        euler_R(eo[15], eo[16], eo[17], R); compose(MB, R, MA);
        px = fmaf(L[5], MA[6], px); py = fmaf(L[5], MA[7], py); pz = fmaf(L[5], MA[8], pz);
        put3(eo, 18, px, py, pz);

        // spine: bone 6 (0->7), bone 7 (7->8)
        euler_R(eo[18], eo[19], eo[20], MA);
        px = L[6] * MA[6]; py = L[6] * MA[7]; pz = L[6] * MA[8];
        put3(eo, 21, px, py, pz);
        euler_R(eo[21], eo[22], eo[23], R); compose(MA, R, M8);
        p8x = fmaf(L[7], M8[6], px); p8y = fmaf(L[7], M8[7], py); p8z = fmaf(L[7], M8[8], pz);
        put3(eo, 24, p8x, p8y, p8z);

        // head: bones 8 (8->9), 9 (9->10) -> joints 9,10
        euler_R(eo[24], eo[25], eo[26], R); compose(M8, R, MA);
        px = fmaf(L[8], MA[6], p8x); py = fmaf(L[8], MA[7], p8y); pz = fmaf(L[8], MA[8], p8z);
        put3(eo, 27, px, py, pz);
        euler_R(eo[27], eo[28], eo[29], R); compose(MA, R, MB);
        px = fmaf(L[9], MB[6], px); py = fmaf(L[9], MB[7], py); pz = fmaf(L[9], MB[8], pz);
        put3(eo, 30, px, py, pz);

        // arm A: bones 10,11,12 (8->11->12->13) -> joints 11,12,13
        euler_R(eo[30], eo[31], eo[32], R); compose(M8, R, MA);
        px = fmaf(L[10], MA[6], p8x); py = fmaf(L[10], MA[7], p8y); pz = fmaf(L[10], MA[8], p8z);
        put3(eo, 33, px, py, pz);
        euler_R(eo[33], eo[34], eo[35], R); compose(MA, R, MB);
        px = fmaf(L[11], MB[6], px); py = fmaf(L[11], MB[7], py); pz = fmaf(L[11], MB[8], pz);
        put3(eo, 36, px, py, pz);
        euler_R(eo[36], eo[37], eo[38], R); compose(MB, R, MA);
        px = fmaf(L[12], MA[6], px); py = fmaf(L[12], MA[7], py); pz = fmaf(L[12], MA[8], pz);
        put3(eo, 39, px, py, pz);

        // arm B: bones 13,14,15 (8->14->15->16) -> joints 14,15,16
        euler_R(eo[39], eo[40], eo[41], R); compose(M8, R, MA);
        px = fmaf(L[13], MA[6], p8x); py = fmaf(L[13], MA[7], p8y); pz = fmaf(L[13], MA[8], p8z);
        put3(eo, 42, px, py, pz);
        euler_R(eo[42], eo[43], eo[44], R); compose(MA, R, MB);
        px = fmaf(L[14], MB[6], px); py = fmaf(L[14], MB[7], py); pz = fmaf(L[14], MB[8], pz);
        put3(eo, 45, px, py, pz);
        euler_R(eo[45], eo[46], eo[47], R); compose(MB, R, MA);
        px = fmaf(L[15], MA[6], px); py = fmaf(L[15], MA[7], py); pz = fmaf(L[15], MA[8], pz);
        put3(eo, 48, px, py, pz);   // o[48..50] -> slots 45..47

        // root joint o[0..2] -> slots 48..50 (never holding live euler data)
        eo[48] = 0.f; eo[49] = 0.f; eo[50] = 0.f;
    }
    __syncthreads();

    // ---- store: scalar, stride-1 lanes in smem (conflict-free) and GMEM ----
    // output float j of sample s lives at slot (j>=3 ? j-3 : j+48)
    {
        float* go = out + (size_t)base * 51;
        const int nf = ns * 51;
#pragma unroll 8
        for (int g = t; g < nf; g += TPB) {
            int s = g / 51;
            int r = g - s * 51;
            int slot = (r >= 3) ? (r - 3) : (r + 48);
            go[g] = s_eo[s * EOSTR + slot];
        }
    }
}

extern "C" void kernel_launch(void* const* d_in, const int* in_sizes, int n_in,
                              void* d_out, int out_size)
{
    const float* euler = (const float*)d_in[0];   // (N,16,3) f32
    const float* blen  = (const float*)d_in[1];   // (N,16,1) f32
    float* out = (float*)d_out;                   // (N,17,3) f32

    const int N = in_sizes[0] / 48;
    const int grid = (N + TPB - 1) / TPB;
    const size_t smem = (size_t)TPB * (EOSTR + BSTR) * sizeof(float); // 34,816 B

    cudaFuncSetAttribute(fk_kernel, cudaFuncAttributeMaxDynamicSharedMemorySize, (int)smem);
    cudaFuncSetAttribute(fk_kernel, cudaFuncAttributePreferredSharedMemoryCarveout,
                         cudaSharedmemCarveoutMaxShared);
    fk_kernel<<<grid, TPB, smem>>>(euler, blen, out, N);
}

// round 7
// speedup vs baseline: 1.2329x; 1.0188x over previous
#include <cuda_runtime.h>

#define TPB 128
// per-sample smem stride (odd => conflict-free rows): euler in, positions out.
// e[0..47] consumed sequentially; o[j..j+2] overwrites slots j-3..j-1;
// root o[0..2] -> slots 48..50 (never hold euler data).
#define EOSTR 51

__device__ __forceinline__ void euler_R(float ax, float ay, float az, float R[9]) {
    float sx, cx, sy, cy, sz, cz;
    __sincosf(ax, &sx, &cx);
    __sincosf(ay, &sy, &cy);
    __sincosf(az, &sz, &cz);
    float sxsy = sx * sy;
    float cxsy = cx * sy;
    R[0] = cy * cz;                 R[1] = -cy * sz;                 R[2] = sy;
    R[3] = fmaf(sxsy, cz, cx * sz); R[4] = fmaf(-sxsy, sz, cx * cz); R[5] = -sx * cy;
    R[6] = fmaf(-cxsy, cz, sx * sz);R[7] = fmaf(cxsy, sz, sx * cz);  R[8] = cx * cy;
}

__device__ __forceinline__ void compose(const float Mp[9], const float R[9], float Mc[9]) {
#pragma unroll
    for (int i = 0; i < 3; i++) {
#pragma unroll
        for (int j = 0; j < 3; j++) {
            Mc[i * 3 + j] = fmaf(Mp[i * 3 + 0], R[0 + j],
                            fmaf(Mp[i * 3 + 1], R[3 + j],
                                 Mp[i * 3 + 2] * R[6 + j]));
        }
    }
}

__device__ __forceinline__ void put3(float* o, int j, float x, float y, float z) {
    o[j - 3] = x; o[j - 2] = y; o[j - 1] = z;
}

__device__ __forceinline__ void fk_compute(float* eo, const float L[16]) {
    float R[9], MA[9], MB[9], M8[9];
    float px, py, pz, p8x, p8y, p8z;

    // leg 1: bones 0,1,2 -> joints 1,2,3 (parent=root, M=I)
    euler_R(eo[0], eo[1], eo[2], MA);
    px = L[0] * MA[6]; py = L[0] * MA[7]; pz = L[0] * MA[8];
    put3(eo, 3, px, py, pz);
    euler_R(eo[3], eo[4], eo[5], R);  compose(MA, R, MB);
    px = fmaf(L[1], MB[6], px); py = fmaf(L[1], MB[7], py); pz = fmaf(L[1], MB[8], pz);
    put3(eo, 6, px, py, pz);
    euler_R(eo[6], eo[7], eo[8], R);  compose(MB, R, MA);
    px = fmaf(L[2], MA[6], px); py = fmaf(L[2], MA[7], py); pz = fmaf(L[2], MA[8], pz);
    put3(eo, 9, px, py, pz);

    // leg 2: bones 3,4,5 -> joints 4,5,6
    euler_R(eo[9], eo[10], eo[11], MA);
    px = L[3] * MA[6]; py = L[3] * MA[7]; pz = L[3] * MA[8];
    put3(eo, 12, px, py, pz);
    euler_R(eo[12], eo[13], eo[14], R); compose(MA, R, MB);
    px = fmaf(L[4], MB[6], px); py = fmaf(L[4], MB[7], py); pz = fmaf(L[4], MB[8], pz);
    put3(eo, 15, px, py, pz);
    euler_R(eo[15], eo[16], eo[17], R); compose(MB, R, MA);
    px = fmaf(L[5], MA[6], px); py = fmaf(L[5], MA[7], py); pz = fmaf(L[5], MA[8], pz);
    put3(eo, 18, px, py, pz);

    // spine: bone 6 (0->7), bone 7 (7->8)
    euler_R(eo[18], eo[19], eo[20], MA);
    px = L[6] * MA[6]; py = L[6] * MA[7]; pz = L[6] * MA[8];
    put3(eo, 21, px, py, pz);
    euler_R(eo[21], eo[22], eo[23], R); compose(MA, R, M8);
    p8x = fmaf(L[7], M8[6], px); p8y = fmaf(L[7], M8[7], py); p8z = fmaf(L[7], M8[8], pz);
    put3(eo, 24, p8x, p8y, p8z);

    // head: bones 8 (8->9), 9 (9->10) -> joints 9,10
    euler_R(eo[24], eo[25], eo[26], R); compose(M8, R, MA);
    px = fmaf(L[8], MA[6], p8x); py = fmaf(L[8], MA[7], p8y); pz = fmaf(L[8], MA[8], p8z);
    put3(eo, 27, px, py, pz);
    euler_R(eo[27], eo[28], eo[29], R); compose(MA, R, MB);
    px = fmaf(L[9], MB[6], px); py = fmaf(L[9], MB[7], py); pz = fmaf(L[9], MB[8], pz);
    put3(eo, 30, px, py, pz);

    // arm A: bones 10,11,12 (8->11->12->13) -> joints 11,12,13
    euler_R(eo[30], eo[31], eo[32], R); compose(M8, R, MA);
    px = fmaf(L[10], MA[6], p8x); py = fmaf(L[10], MA[7], p8y); pz = fmaf(L[10], MA[8], p8z);
    put3(eo, 33, px, py, pz);
    euler_R(eo[33], eo[34], eo[35], R); compose(MA, R, MB);
    px = fmaf(L[11], MB[6], px); py = fmaf(L[11], MB[7], py); pz = fmaf(L[11], MB[8], pz);
    put3(eo, 36, px, py, pz);
    euler_R(eo[36], eo[37], eo[38], R); compose(MB, R, MA);
    px = fmaf(L[12], MA[6], px); py = fmaf(L[12], MA[7], py); pz = fmaf(L[12], MA[8], pz);
    put3(eo, 39, px, py, pz);

    // arm B: bones 13,14,15 (8->14->15->16) -> joints 14,15,16
    euler_R(eo[39], eo[40], eo[41], R); compose(M8, R, MA);
    px = fmaf(L[13], MA[6], p8x); py = fmaf(L[13], MA[7], p8y); pz = fmaf(L[13], MA[8], p8z);
    put3(eo, 42, px, py, pz);
    euler_R(eo[42], eo[43], eo[44], R); compose(MA, R, MB);
    px = fmaf(L[14], MB[6], px); py = fmaf(L[14], MB[7], py); pz = fmaf(L[14], MB[8], pz);
    put3(eo, 45, px, py, pz);
    euler_R(eo[45], eo[46], eo[47], R); compose(MB, R, MA);
    px = fmaf(L[15], MA[6], px); py = fmaf(L[15], MA[7], py); pz = fmaf(L[15], MA[8], pz);
    put3(eo, 48, px, py, pz);   // -> slots 45..47

    // root joint o[0..2] -> slots 48..50
    eo[48] = 0.f; eo[49] = 0.f; eo[50] = 0.f;
}

extern "C" __global__ void __launch_bounds__(TPB, 8)
fk_kernel(const float* __restrict__ euler, const float* __restrict__ blen,
          float* __restrict__ out, int N)
{
    extern __shared__ float sm[];
    float* s_eo = sm;                      // TPB * EOSTR

    const int t    = threadIdx.x;
    const int base = blockIdx.x * TPB;
    const int ns   = min(TPB, N - base);
    const bool full = (ns == TPB);

    // ---- euler staging: float4 LDG (12 independent loads -> high MLP) ----
    {
        const float4* ge = (const float4*)(euler + (size_t)base * 48);
        if (full) {
#pragma unroll
            for (int k = 0; k < 12; k++) {
                int i = t + k * TPB;
                float4 v = ge[i];
                int s = i / 12, r = i - s * 12;
                float* p = s_eo + s * EOSTR + r * 4;
                p[0] = v.x; p[1] = v.y; p[2] = v.z; p[3] = v.w;
            }
        } else {
            const int ne4 = ns * 12;
            for (int i = t; i < ne4; i += TPB) {
                float4 v = ge[i];
                int s = i / 12, r = i - s * 12;
                float* p = s_eo + s * EOSTR + r * 4;
                p[0] = v.x; p[1] = v.y; p[2] = v.z; p[3] = v.w;
            }
        }
    }

    // ---- bone lengths: direct per-thread float4 LDG (adds MLP, no smem) ----
    float L[16];
    if (t < ns) {
        const float4* gb = (const float4*)(blen + (size_t)(base + t) * 16);
        float4 a = gb[0], b = gb[1], c = gb[2], d = gb[3];
        L[0]=a.x; L[1]=a.y; L[2]=a.z;  L[3]=a.w;
        L[4]=b.x; L[5]=b.y; L[6]=b.z;  L[7]=b.w;
        L[8]=c.x; L[9]=c.y; L[10]=c.z; L[11]=c.w;
        L[12]=d.x; L[13]=d.y; L[14]=d.z; L[15]=d.w;
    }
    __syncthreads();

    // ---- per-sample FK (in-place: o[j] -> slot j-3; conflict-free rows) ----
    if (t < ns) {
        fk_compute(s_eo + t * EOSTR, L);
    }
    __syncthreads();

    // ---- store: scalar, stride-1 lanes (conflict-free LDS, coalesced STG),
    //      incremental (s,r) bookkeeping instead of division ----
    {
        float* go = out + (size_t)base * 51;
        int s = t / 51;              // t < 128 -> s in {0,1,2}
        int r = t - s * 51;
        if (full) {
            int g = t;
#pragma unroll 3
            for (int j = 0; j < 51; j++) {      // 51*128 = 6528 floats exactly
                int slot = (r >= 3) ? (r - 3) : (r + 48);
                go[g] = s_eo[s * EOSTR + slot];
                g += TPB;
                r += 26; s += 2;                 // 128 = 2*51 + 26
                if (r >= 51) { r -= 51; s++; }
            }
        } else {
            const int nf = ns * 51;
            for (int g = t; g < nf; g += TPB) {
                int slot = (r >= 3) ? (r - 3) : (r + 48);
                go[g] = s_eo[s * EOSTR + slot];
                r += 26; s += 2;
                if (r >= 51) { r -= 51; s++; }
            }
        }
    }
}

extern "C" void kernel_launch(void* const* d_in, const int* in_sizes, int n_in,
                              void* d_out, int out_size)
{
    const float* euler = (const float*)d_in[0];   // (N,16,3) f32
    const float* blen  = (const float*)d_in[1];   // (N,16,1) f32
    float* out = (float*)d_out;                   // (N,17,3) f32

    const int N = in_sizes[0] / 48;
    const int grid = (N + TPB - 1) / TPB;
    const size_t smem = (size_t)TPB * EOSTR * sizeof(float); // 26,112 B -> 8 blocks/SM

    cudaFuncSetAttribute(fk_kernel, cudaFuncAttributeMaxDynamicSharedMemorySize, (int)smem);
    cudaFuncSetAttribute(fk_kernel, cudaFuncAttributePreferredSharedMemoryCarveout,
                         cudaSharedmemCarveoutMaxShared);
    fk_kernel<<<grid, TPB, smem>>>(euler, blen, out, N);
}

// round 8
// speedup vs baseline: 1.3199x; 1.0706x over previous
#include <cuda_runtime.h>

#define TPB 128
// Per-sample smem stride 51 (odd => conflict-free rows). Euler floats of bone i
// live at slots 3i..3i+2. Joint i+1's output is written IN ITS NATURAL SLOT
// 3(i+1)..3(i+1)+2 (bone i+1's euler, prefetched to registers one bone ahead).
// Root joint -> slots 0..2. After compute, smem == output layout exactly.
#define EOSTR 51

__device__ __forceinline__ void euler_R(float ax, float ay, float az, float R[9]) {
    float sx, cx, sy, cy, sz, cz;
    __sincosf(ax, &sx, &cx);
    __sincosf(ay, &sy, &cy);
    __sincosf(az, &sz, &cz);
    float sxsy = sx * sy;
    float cxsy = cx * sy;
    R[0] = cy * cz;                 R[1] = -cy * sz;                 R[2] = sy;
    R[3] = fmaf(sxsy, cz, cx * sz); R[4] = fmaf(-sxsy, sz, cx * cz); R[5] = -sx * cy;
    R[6] = fmaf(-cxsy, cz, sx * sz);R[7] = fmaf(cxsy, sz, sx * cz);  R[8] = cx * cy;
}

__device__ __forceinline__ void compose(const float Mp[9], const float R[9], float Mc[9]) {
#pragma unroll
    for (int i = 0; i < 3; i++) {
#pragma unroll
        for (int j = 0; j < 3; j++) {
            Mc[i * 3 + j] = fmaf(Mp[i * 3 + 0], R[0 + j],
                            fmaf(Mp[i * 3 + 1], R[3 + j],
                                 Mp[i * 3 + 2] * R[6 + j]));
        }
    }
}

// prefetch euler triple of bone b into (nx,ny,nz)
#define PREFETCH(b) nx = eo[3*(b)]; ny = eo[3*(b)+1]; nz = eo[3*(b)+2]
// store joint j position at its natural output slot 3j..3j+2
#define STOREJ(j, X, Y, Z) eo[3*(j)] = (X); eo[3*(j)+1] = (Y); eo[3*(j)+2] = (Z)
#define SHIFT() ax = nx; ay = ny; az = nz

__device__ __forceinline__ void fk_compute(float* eo, const float L[16]) {
    float ax = eo[0], ay = eo[1], az = eo[2];
    float nx, ny, nz;
    float R[9], MA[9], MB[9], M8[9];
    float px, py, pz, p8x, p8y, p8z;

    // ---- leg 1: bones 0,1,2 -> joints 1,2,3 (parent = root, M = I) ----
    PREFETCH(1);
    euler_R(ax, ay, az, MA);
    px = L[0] * MA[6]; py = L[0] * MA[7]; pz = L[0] * MA[8];
    STOREJ(1, px, py, pz); SHIFT();

    PREFETCH(2);
    euler_R(ax, ay, az, R); compose(MA, R, MB);
    px = fmaf(L[1], MB[6], px); py = fmaf(L[1], MB[7], py); pz = fmaf(L[1], MB[8], pz);
    STOREJ(2, px, py, pz); SHIFT();

    PREFETCH(3);
    euler_R(ax, ay, az, R); compose(MB, R, MA);
    px = fmaf(L[2], MA[6], px); py = fmaf(L[2], MA[7], py); pz = fmaf(L[2], MA[8], pz);
    STOREJ(3, px, py, pz); SHIFT();

    // ---- leg 2: bones 3,4,5 -> joints 4,5,6 ----
    PREFETCH(4);
    euler_R(ax, ay, az, MA);
    px = L[3] * MA[6]; py = L[3] * MA[7]; pz = L[3] * MA[8];
    STOREJ(4, px, py, pz); SHIFT();

    PREFETCH(5);
    euler_R(ax, ay, az, R); compose(MA, R, MB);
    px = fmaf(L[4], MB[6], px); py = fmaf(L[4], MB[7], py); pz = fmaf(L[4], MB[8], pz);
    STOREJ(5, px, py, pz); SHIFT();

    PREFETCH(6);
    euler_R(ax, ay, az, R); compose(MB, R, MA);
    px = fmaf(L[5], MA[6], px); py = fmaf(L[5], MA[7], py); pz = fmaf(L[5], MA[8], pz);
    STOREJ(6, px, py, pz); SHIFT();

    // ---- spine: bone 6 (0->7), bone 7 (7->8) ----
    PREFETCH(7);
    euler_R(ax, ay, az, MA);
    px = L[6] * MA[6]; py = L[6] * MA[7]; pz = L[6] * MA[8];
    STOREJ(7, px, py, pz); SHIFT();

    PREFETCH(8);
    euler_R(ax, ay, az, R); compose(MA, R, M8);
    p8x = fmaf(L[7], M8[6], px); p8y = fmaf(L[7], M8[7], py); p8z = fmaf(L[7], M8[8], pz);
    STOREJ(8, p8x, p8y, p8z); SHIFT();

    // ---- head: bones 8 (8->9), 9 (9->10) ----
    PREFETCH(9);
    euler_R(ax, ay, az, R); compose(M8, R, MA);
    px = fmaf(L[8], MA[6], p8x); py = fmaf(L[8], MA[7], p8y); pz = fmaf(L[8], MA[8], p8z);
    STOREJ(9, px, py, pz); SHIFT();

    PREFETCH(10);
    euler_R(ax, ay, az, R); compose(MA, R, MB);
    px = fmaf(L[9], MB[6], px); py = fmaf(L[9], MB[7], py); pz = fmaf(L[9], MB[8], pz);
    STOREJ(10, px, py, pz); SHIFT();

    // ---- arm A: bones 10,11,12 (8->11->12->13) ----
    PREFETCH(11);
    euler_R(ax, ay, az, R); compose(M8, R, MA);
    px = fmaf(L[10], MA[6], p8x); py = fmaf(L[10], MA[7], p8y); pz = fmaf(L[10], MA[8], p8z);
    STOREJ(11, px, py, pz); SHIFT();

    PREFETCH(12);
    euler_R(ax, ay, az, R); compose(MA, R, MB);
    px = fmaf(L[11], MB[6], px); py = fmaf(L[11], MB[7], py); pz = fmaf(L[11], MB[8], pz);
    STOREJ(12, px, py, pz); SHIFT();

    PREFETCH(13);
    euler_R(ax, ay, az, R); compose(MB, R, MA);
    px = fmaf(L[12], MA[6], px); py = fmaf(L[12], MA[7], py); pz = fmaf(L[12], MA[8], pz);
    STOREJ(13, px, py, pz); SHIFT();

    // ---- arm B: bones 13,14,15 (8->14->15->16) ----
    PREFETCH(14);
    euler_R(ax, ay, az, R); compose(M8, R, MA);
    px = fmaf(L[13], MA[6], p8x); py = fmaf(L[13], MA[7], p8y); pz = fmaf(L[13], MA[8], p8z);
    STOREJ(14, px, py, pz); SHIFT();

    PREFETCH(15);
    euler_R(ax, ay, az, R); compose(MA, R, MB);
    px = fmaf(L[14], MB[6], px); py = fmaf(L[14], MB[7], py); pz = fmaf(L[14], MB[8], pz);
    STOREJ(15, px, py, pz); SHIFT();

    // bone 15 (no prefetch; euler already in registers)
    euler_R(ax, ay, az, R); compose(MB, R, MA);
    px = fmaf(L[15], MA[6], px); py = fmaf(L[15], MA[7], py); pz = fmaf(L[15], MA[8], pz);
    STOREJ(16, px, py, pz);

    // root joint -> slots 0..2 (its euler was consumed first)
    eo[0] = 0.f; eo[1] = 0.f; eo[2] = 0.f;
}

extern "C" __global__ void __launch_bounds__(TPB, 8)
fk_kernel(const float* __restrict__ euler, const float* __restrict__ blen,
          float* __restrict__ out, int N)
{
    extern __shared__ float sm[];
    float* s_eo = sm;                      // TPB * EOSTR

    const int t    = threadIdx.x;
    const int base = blockIdx.x * TPB;
    const int ns   = min(TPB, N - base);
    const bool full = (ns == TPB);

    // ---- euler staging: float4 LDG (12 independent loads -> high MLP) ----
    {
        const float4* ge = (const float4*)(euler + (size_t)base * 48);
        if (full) {
#pragma unroll
            for (int k = 0; k < 12; k++) {
                int i = t + k * TPB;
                float4 v = ge[i];
                int s = i / 12, r = i - s * 12;
                float* p = s_eo + s * EOSTR + r * 4;
                p[0] = v.x; p[1] = v.y; p[2] = v.z; p[3] = v.w;
            }
        } else {
            const int ne4 = ns * 12;
            for (int i = t; i < ne4; i += TPB) {
                float4 v = ge[i];
                int s = i / 12, r = i - s * 12;
                float* p = s_eo + s * EOSTR + r * 4;
                p[0] = v.x; p[1] = v.y; p[2] = v.z; p[3] = v.w;
            }
        }
    }

    // ---- bone lengths: direct per-thread float4 LDG (adds MLP, no smem) ----
    float L[16];
    if (t < ns) {
        const float4* gb = (const float4*)(blen + (size_t)(base + t) * 16);
        float4 a = gb[0], b = gb[1], c = gb[2], d = gb[3];
        L[0]=a.x;  L[1]=a.y;  L[2]=a.z;  L[3]=a.w;
        L[4]=b.x;  L[5]=b.y;  L[6]=b.z;  L[7]=b.w;
        L[8]=c.x;  L[9]=c.y;  L[10]=c.z; L[11]=c.w;
        L[12]=d.x; L[13]=d.y; L[14]=d.z; L[15]=d.w;
    }
    __syncthreads();

    // ---- per-sample FK: outputs land at natural slots -> smem == out layout ----
    if (t < ns) {
        fk_compute(s_eo + t * EOSTR, L);
    }
    __syncthreads();

    // ---- store: pure linear copy, float4, zero index math ----
    {
        float* go = out + (size_t)base * 51;
        if (full) {
            // 51*128 = 6528 floats = 1632 float4 = 12*128 + 96
            float4* go4 = (float4*)go;
            const float4* se4 = (const float4*)s_eo;
#pragma unroll
            for (int k = 0; k < 12; k++)
                go4[t + k * TPB] = se4[t + k * TPB];
            if (t < 96)
                go4[t + 12 * TPB] = se4[t + 12 * TPB];
        } else {
            const int nf = ns * 51;
            for (int g = t; g < nf; g += TPB)
                go[g] = s_eo[g];
        }
    }
}

extern "C" void kernel_launch(void* const* d_in, const int* in_sizes, int n_in,
                              void* d_out, int out_size)
{
    const float* euler = (const float*)d_in[0];   // (N,16,3) f32
    const float* blen  = (const float*)d_in[1];   // (N,16,1) f32
    float* out = (float*)d_out;                   // (N,17,3) f32

    const int N = in_sizes[0] / 48;
    const int grid = (N + TPB - 1) / TPB;
    const size_t smem = (size_t)TPB * EOSTR * sizeof(float); // 26,112 B -> 8 blocks/SM

    cudaFuncSetAttribute(fk_kernel, cudaFuncAttributeMaxDynamicSharedMemorySize, (int)smem);
    cudaFuncSetAttribute(fk_kernel, cudaFuncAttributePreferredSharedMemoryCarveout,
                         cudaSharedmemCarveoutMaxShared);
    fk_kernel<<<grid, TPB, smem>>>(euler, blen, out, N);
}